// round 1
// baseline (speedup 1.0000x reference)
#include <cuda_runtime.h>
#include <cstdint>
#include <cstdio>

// Problem constants (fixed by setup_inputs)
#define BATCH   4
#define N_DOWN  16384
#define N_UP    65536
#define C_DOWN  256
#define C_UP    128
#define C_OUT   128
#define M1 (BATCH * N_DOWN)   // 65536 rows for GEMM1
#define M2 (BATCH * N_UP)     // 262144 rows for GEMM2

// GEMM tiling
#define BM 128
#define BN 128
#define BK 32
#define KTOT 256
#define AS_STRIDE 136                      // 136 % 32 == 8 -> conflict-free frag loads
#define AS_STAGE (BK * AS_STRIDE)          // 4352 floats
#define BS_STAGE (BK * BN)                 // 4096 floats
#define SMEM_BYTES ((2 * AS_STAGE + 2 * BS_STAGE) * 4 + 512)

// -------------------- device scratch (no allocation allowed) --------------------
__device__ float g_y[(size_t)M1 * C_UP];          // LReLU(x_down @ W_lin)
__device__ int   g_idx[M2];                       // flattened gather indices
__device__ float g_Wlin_r[C_DOWN * C_UP];         // tf32-RNA-rounded weights
__device__ float g_Wfus_r[2 * C_UP * C_OUT];
__device__ int   g_is64;                          // up_idx dtype flag

// -------------------- helpers --------------------
__device__ __forceinline__ float tf32_rna(float x) {
    unsigned u;
    asm("cvt.rna.tf32.f32 %0, %1;" : "=r"(u) : "f"(x));
    return __uint_as_float(u);
}

__device__ __forceinline__ void cpa16(void* s, const void* g) {
    unsigned sa = (unsigned)__cvta_generic_to_shared(s);
    asm volatile("cp.async.cg.shared.global [%0], [%1], 16;" :: "r"(sa), "l"(g));
}

__device__ __forceinline__ float lrelu(float v) { return v > 0.f ? v : 0.1f * v; }

#define MMA_TF32(d, a, b)                                                          \
    asm volatile(                                                                  \
        "mma.sync.aligned.m16n8k8.row.col.f32.tf32.tf32.f32 "                      \
        "{%0,%1,%2,%3},{%4,%5,%6,%7},{%8,%9},{%0,%1,%2,%3};"                       \
        : "+f"(d[0]), "+f"(d[1]), "+f"(d[2]), "+f"(d[3])                           \
        : "r"(a[0]), "r"(a[1]), "r"(a[2]), "r"(a[3]), "r"(b[0]), "r"(b[1]))

// -------------------- prep kernels --------------------
// Detect whether up_idx is int64 or int32. For int64, every "odd" 32-bit word
// (hi half of a nonneg index < 16384) is zero. For int32, odd words are random
// indices and are essentially never all zero.
__global__ void k_detect_idx(const unsigned* __restrict__ w, int n_idx) {
    __shared__ unsigned red[256];
    unsigned acc = 0;
    int half = n_idx >> 1;
    for (int i = threadIdx.x; i < half; i += blockDim.x) acc |= w[2 * i + 1];
    red[threadIdx.x] = acc;
    __syncthreads();
    for (int s = 128; s > 0; s >>= 1) {
        if ((int)threadIdx.x < s) red[threadIdx.x] |= red[threadIdx.x + s];
        __syncthreads();
    }
    if (threadIdx.x == 0) g_is64 = (red[0] == 0u) ? 1 : 0;
}

// Convert up_idx to flat int32 row index into g_y (includes batch offset).
__global__ void k_convert_idx(const void* __restrict__ p, int n_idx) {
    int i = blockIdx.x * blockDim.x + threadIdx.x;
    if (i >= n_idx) return;
    int v = g_is64 ? (int)((const long long*)p)[i] : ((const int*)p)[i];
    g_idx[i] = (i >> 16) * N_DOWN + v;   // i>>16 == i / N_UP (N_UP = 65536)
}

// Round both weight matrices to tf32 (RNA) once.
__global__ void k_round_w(const float* __restrict__ Wlin, const float* __restrict__ Wfus) {
    int i = blockIdx.x * blockDim.x + threadIdx.x;
    if (i < C_DOWN * C_UP) g_Wlin_r[i] = tf32_rna(Wlin[i]);
    if (i < 2 * C_UP * C_OUT) g_Wfus_r[i] = tf32_rna(Wfus[i]);
}

// -------------------- fused GEMM --------------------
// MODE 0: y = LReLU(x_down[65536,256] @ Wlin[256,128] + b_lin)      -> g_y
// MODE 1: out = LReLU([x_up | gather(g_y)] [262144,256] @ Wfus + b) -> d_out
template <int MODE>
__device__ __forceinline__ const float* a_src(const float* __restrict__ A0,
                                              int rowg, const int* sIdx,
                                              int rloc, int half, int c) {
    if (MODE == 0) {
        return A0 + (size_t)rowg * KTOT + c * BK + half * 16;
    } else {
        if (c < 4) return A0 + (size_t)rowg * C_UP + c * BK + half * 16;
        return g_y + (size_t)sIdx[rloc] * C_UP + (c - 4) * BK + half * 16;
    }
}

__device__ __forceinline__ void store_a(float* __restrict__ Ast, int rloc, int half,
                                        const float4* aA) {
#pragma unroll
    for (int j = 0; j < 4; j++) {
        int kl = half * 16 + j * 4;
        float4 v = aA[j];
        Ast[(kl + 0) * AS_STRIDE + rloc] = tf32_rna(v.x);
        Ast[(kl + 1) * AS_STRIDE + rloc] = tf32_rna(v.y);
        Ast[(kl + 2) * AS_STRIDE + rloc] = tf32_rna(v.z);
        Ast[(kl + 3) * AS_STRIDE + rloc] = tf32_rna(v.w);
    }
}

template <int MODE>
__global__ __launch_bounds__(256, 1) void gemm_tf32(const float* __restrict__ A0,
                                                    const float* __restrict__ bias,
                                                    float* __restrict__ outp) {
    extern __shared__ float smem[];
    float* As = smem;                       // [2][BK][AS_STRIDE]
    float* Bs = smem + 2 * AS_STAGE;        // [2][BK][BN]
    int* sIdx = (int*)(Bs + 2 * BS_STAGE);  // [BM]

    const float* Wr = (MODE == 0) ? g_Wlin_r : g_Wfus_r;
    float* out = (MODE == 0) ? g_y : outp;

    const int tid = threadIdx.x;
    const int lane = tid & 31, wid = tid >> 5;
    const int g = lane >> 2, t4 = lane & 3;
    const int mb = (wid >> 2) * 64, nb = (wid & 3) * 32;
    const int rowBlk = blockIdx.x * BM;

    if (MODE == 1 && tid < BM) sIdx[tid] = g_idx[rowBlk + tid];

    const int rloc = tid >> 1;
    const int half = tid & 1;
    const int rowg = rowBlk + rloc;

    float acc[4][4][4];
#pragma unroll
    for (int mt = 0; mt < 4; mt++)
#pragma unroll
        for (int nt = 0; nt < 4; nt++)
#pragma unroll
            for (int e = 0; e < 4; e++) acc[mt][nt][e] = 0.f;

    float4 aA[4];

    // -------- prologue: stage 0 --------
    {
        const float* s = a_src<MODE>(A0, rowg, sIdx, rloc, half, 0);
#pragma unroll
        for (int j = 0; j < 4; j++) aA[j] = ((const float4*)s)[j];
#pragma unroll
        for (int i = 0; i < 4; i++) {
            int f = tid + i * 256;
            cpa16(Bs + f * 4, Wr + f * 4);
        }
        asm volatile("cp.async.commit_group;" ::: "memory");
        store_a(As, rloc, half, aA);
        asm volatile("cp.async.wait_group 0;" ::: "memory");
        __syncthreads();
    }

    // -------- main loop over 8 K-chunks --------
#pragma unroll 1
    for (int c = 0; c < 8; ++c) {
        const int cur = c & 1;
        const float* Asc = As + cur * AS_STAGE;
        const float* Bsc = Bs + cur * BS_STAGE;

        if (c < 7) {
            const float* s = a_src<MODE>(A0, rowg, sIdx, rloc, half, c + 1);
#pragma unroll
            for (int j = 0; j < 4; j++) aA[j] = ((const float4*)s)[j];
            const float* wsrc = Wr + (size_t)(c + 1) * BK * BN;
            float* bdst = Bs + (cur ^ 1) * BS_STAGE;
#pragma unroll
            for (int i = 0; i < 4; i++) {
                int f = tid + i * 256;
                cpa16(bdst + f * 4, wsrc + f * 4);
            }
            asm volatile("cp.async.commit_group;" ::: "memory");
        }

#pragma unroll
        for (int ks = 0; ks < 4; ++ks) {
            const float* Ak = Asc + (ks * 8 + t4) * AS_STRIDE;
            unsigned a[4][4];
#pragma unroll
            for (int mt = 0; mt < 4; mt++) {
                int r = mb + mt * 16 + g;
                a[mt][0] = __float_as_uint(Ak[r]);
                a[mt][1] = __float_as_uint(Ak[r + 8]);
                a[mt][2] = __float_as_uint(Ak[4 * AS_STRIDE + r]);
                a[mt][3] = __float_as_uint(Ak[4 * AS_STRIDE + r + 8]);
            }
            unsigned b[4][2];
            const float* Bk = Bsc + (ks * 8 + t4) * BN;
#pragma unroll
            for (int nt = 0; nt < 4; nt++) {
                int cc = nb + nt * 8 + g;
                b[nt][0] = __float_as_uint(Bk[cc]);
                b[nt][1] = __float_as_uint(Bk[4 * BN + cc]);
            }
#pragma unroll
            for (int mt = 0; mt < 4; mt++)
#pragma unroll
                for (int nt = 0; nt < 4; nt++) MMA_TF32(acc[mt][nt], a[mt], b[nt]);
        }

        if (c < 7) {
            store_a(As + (cur ^ 1) * AS_STAGE, rloc, half, aA);
            asm volatile("cp.async.wait_group 0;" ::: "memory");
        }
        __syncthreads();
    }

    // -------- epilogue: bias + LeakyReLU + store --------
#pragma unroll
    for (int nt = 0; nt < 4; nt++) {
        int col = nb + nt * 8 + 2 * t4;
        float bv0 = bias[col], bv1 = bias[col + 1];
#pragma unroll
        for (int mt = 0; mt < 4; mt++) {
            int row = rowBlk + mb + mt * 16 + g;
            float* a4 = acc[mt][nt];
            float2 v0, v1;
            v0.x = lrelu(a4[0] + bv0);
            v0.y = lrelu(a4[1] + bv1);
            v1.x = lrelu(a4[2] + bv0);
            v1.y = lrelu(a4[3] + bv1);
            *(float2*)(out + (size_t)row * 128 + col) = v0;
            *(float2*)(out + (size_t)(row + 8) * 128 + col) = v1;
        }
    }
}

// -------------------- launch --------------------
extern "C" void kernel_launch(void* const* d_in, const int* in_sizes, int n_in,
                              void* d_out, int out_size) {
    const float* x_down = (const float*)d_in[0];
    const float* x_up   = (const float*)d_in[1];
    const void*  up_idx = d_in[2];
    const float* Wlin   = (const float*)d_in[3];
    const float* blin   = (const float*)d_in[4];
    const float* Wfus   = (const float*)d_in[5];
    const float* bfus   = (const float*)d_in[6];
    float* out = (float*)d_out;

    cudaFuncSetAttribute(gemm_tf32<0>, cudaFuncAttributeMaxDynamicSharedMemorySize, SMEM_BYTES);
    cudaFuncSetAttribute(gemm_tf32<1>, cudaFuncAttributeMaxDynamicSharedMemorySize, SMEM_BYTES);

    k_detect_idx<<<1, 256>>>((const unsigned*)up_idx, M2);
    k_convert_idx<<<M2 / 256, 256>>>(up_idx, M2);
    k_round_w<<<(C_DOWN * C_UP + 255) / 256, 256>>>(Wlin, Wfus);

    gemm_tf32<0><<<M1 / BM, 256, SMEM_BYTES>>>(x_down, blin, nullptr);
    gemm_tf32<1><<<M2 / BM, 256, SMEM_BYTES>>>(x_up, bfus, out);
}

// round 4
// speedup vs baseline: 1.6970x; 1.6970x over previous
#include <cuda_runtime.h>
#include <cstdint>

// ---------------- problem constants ----------------
#define N_DOWN  16384
#define M1 65536              // rows GEMM1 (4*16384), K=256
#define M2 262144             // rows GEMM2 (4*65536), K=256
#define BM 256
#define BN 128
#define BK 32
#define THREADS 512
#define GRID 148
#define NTILES1 (M1 / BM)     // 256
#define NTILES2 (M2 / BM)     // 1024

// ---------------- smem layout (bytes) ----------------
#define OFF_W    0            // 128KB: W fragment image (resident)
#define OFF_A    131072       // 2 x 32KB A stages (row-major, 16B-chunk XOR swizzle)
#define OFF_IDX  196608       // 256 ints
#define OFF_BIAS 197632       // 128 floats
#define SMEM_BYTES 198144

// ---------------- device scratch ----------------
__device__ __align__(256) float g_y[(size_t)M1 * 128];   // rna(LReLU(x_down@Wlin+b))
__device__ __align__(256) float g_Wf1[32768];            // Wlin fragment-packed
__device__ __align__(256) float g_Wf2[32768];            // Wfus fragment-packed
__device__ int g_idx[M2];
__device__ unsigned g_hibits;

// ---------------- helpers ----------------
__device__ __forceinline__ float tf32_rna(float x) {
    unsigned u; asm("cvt.rna.tf32.f32 %0, %1;" : "=r"(u) : "f"(x));
    return __uint_as_float(u);
}
__device__ __forceinline__ uint32_t rna_u(float x) {
    unsigned u; asm("cvt.rna.tf32.f32 %0, %1;" : "=r"(u) : "f"(x));
    return u;
}
__device__ __forceinline__ float lrelu(float v) { return v > 0.f ? v : 0.1f * v; }

__device__ __forceinline__ uint32_t smem_u32(const void* p) {
    uint32_t a;
    asm("{ .reg .u64 t; cvta.to.shared.u64 t, %1; cvt.u32.u64 %0, t; }" : "=r"(a) : "l"(p));
    return a;
}
__device__ __forceinline__ void cpa16(uint32_t saddr, const void* g) {
    asm volatile("cp.async.cg.shared.global [%0], [%1], 16;" :: "r"(saddr), "l"(g));
}
#define CP_COMMIT() asm volatile("cp.async.commit_group;" ::: "memory")
#define CP_WAIT1()  asm volatile("cp.async.wait_group 1;" ::: "memory")
#define CP_WAIT0()  asm volatile("cp.async.wait_group 0;" ::: "memory")

#define MMA_TF32(d, a, b0, b1)                                                     \
    asm volatile(                                                                  \
        "mma.sync.aligned.m16n8k8.row.col.f32.tf32.tf32.f32 "                      \
        "{%0,%1,%2,%3},{%4,%5,%6,%7},{%8,%9},{%0,%1,%2,%3};"                       \
        : "+f"((d)[0]), "+f"((d)[1]), "+f"((d)[2]), "+f"((d)[3])                   \
        : "r"((a)[0]), "r"((a)[1]), "r"((a)[2]), "r"((a)[3]), "r"(b0), "r"(b1))

// ---------------- prep kernels ----------------
__global__ void k_zero() { g_hibits = 0u; }

// OR-reduce all odd 32-bit words of up_idx (hi halves if int64). Zero -> int64.
__global__ void k_detect(const unsigned* __restrict__ w, int half) {
    __shared__ unsigned red[256];
    unsigned acc = 0;
    for (int i = blockIdx.x * blockDim.x + threadIdx.x; i < half; i += gridDim.x * blockDim.x)
        acc |= w[2 * i + 1];
    red[threadIdx.x] = acc;
    __syncthreads();
    for (int s = 128; s > 0; s >>= 1) {
        if ((int)threadIdx.x < s) red[threadIdx.x] |= red[threadIdx.x + s];
        __syncthreads();
    }
    if (threadIdx.x == 0 && red[0]) atomicOr(&g_hibits, red[0]);
}

__global__ void k_convert(const void* __restrict__ p, int n_idx) {
    int i = blockIdx.x * blockDim.x + threadIdx.x;
    if (i >= n_idx) return;
    int is64 = (g_hibits == 0u);
    int v = is64 ? (int)((const long long*)p)[i] : ((const int*)p)[i];
    g_idx[i] = (i >> 16) * N_DOWN + v;   // batch = i / 65536
}

// Pack W[k][n] (256x128) into fragment order, tf32-RNA rounded.
// float index i: e=i&3, lane=(i>>2)&31, q=(i>>7)&7, kk=i>>10
// p=e>>1, hb=e&1; n=(2q+p)*8 + lane>>2; k = kk*8 + (lane&3) + hb*4
__global__ void k_prep_w(const float* __restrict__ Wlin, const float* __restrict__ Wfus) {
    int i = blockIdx.x * blockDim.x + threadIdx.x;   // 0..32767
    int e = i & 3, lane = (i >> 2) & 31, q = (i >> 7) & 7, kk = i >> 10;
    int p = e >> 1, hb = e & 1;
    int n = (2 * q + p) * 8 + (lane >> 2);
    int k = kk * 8 + (lane & 3) + hb * 4;
    g_Wf1[i] = tf32_rna(Wlin[k * 128 + n]);
    g_Wf2[i] = tf32_rna(Wfus[k * 128 + n]);
}

// ---------------- persistent tf32 GEMM (mma.sync) ----------------
// MODE 0: g_y = rna(LReLU(x_down[65536,256] @ Wlin + b))
// MODE 1: out =      LReLU([x_up | gather(g_y)][262144,256] @ Wfus + b)
template <int MODE>
__device__ __forceinline__ void issue_stage(char* smc, int buf, int c, int tid,
                                            const float* __restrict__ A0, int rbase) {
    const int row = tid >> 1, half = tid & 1;
    const float* src;
    if (MODE == 0) {
        src = A0 + (size_t)(rbase + row) * 256 + c * 32 + half * 16;
    } else if (c < 4) {
        src = A0 + (size_t)(rbase + row) * 128 + c * 32 + half * 16;
    } else {
        int gr = ((const int*)(smc + OFF_IDX))[row];
        src = g_y + (size_t)gr * 128 + (c - 4) * 32 + half * 16;
    }
    uint32_t dst = smem_u32(smc + OFF_A + buf * 32768) + row * 128;
    const int cb = half * 4, sw = row & 7;
#pragma unroll
    for (int j = 0; j < 4; j++)
        cpa16(dst + ((cb + j) ^ sw) * 16, src + j * 4);
}

template <int MODE>
__global__ __launch_bounds__(THREADS, 1) void gemm_tf32(const float* __restrict__ A0,
                                                        const float* __restrict__ bias,
                                                        float* __restrict__ outp) {
    extern __shared__ char smc[];
    const int tid = threadIdx.x;
    const int lane = tid & 31, wid = tid >> 5;
    const int g = lane >> 2, t4 = lane & 3;
    const int mrow = (wid & 7) * 32;          // warp M offset (32 rows)
    const int ncol = (wid >> 3) * 64;         // warp N offset (64 cols)
    const int qbase = (wid >> 3) * 4;         // B fragment group base

    const float* Wg = (MODE == 0) ? g_Wf1 : g_Wf2;
    float* out = (MODE == 0) ? g_y : outp;
    const int ntiles = (MODE == 0) ? NTILES1 : NTILES2;

    // resident W fragment image: 128KB linear cp.async
    {
        uint32_t wdst = smem_u32(smc + OFF_W);
#pragma unroll
        for (int j = 0; j < 16; j++) {
            int ch = j * THREADS + tid;
            cpa16(wdst + ch * 16, Wg + ch * 4);
        }
        CP_COMMIT();
        if (tid < 128) ((float*)(smc + OFF_BIAS))[tid] = bias[tid];
    }

    for (int t = blockIdx.x; t < ntiles; t += GRID) {
        const int rbase = t * BM;
        if (MODE == 1 && tid < BM) ((int*)(smc + OFF_IDX))[tid] = g_idx[rbase + tid];

        // prologue: stages 0,1
        issue_stage<MODE>(smc, 0, 0, tid, A0, rbase);
        CP_COMMIT();
        // NOTE: MODE 1 stage-1 uses x_up only (c=1 < 4) -> no sIdx dependency
        issue_stage<MODE>(smc, 1, 1, tid, A0, rbase);
        CP_COMMIT();
        CP_WAIT1();
        __syncthreads();   // stage 0 ready everywhere; sIdx/bias visible

        float acc[2][8][4];
#pragma unroll
        for (int mt = 0; mt < 2; mt++)
#pragma unroll
            for (int nt = 0; nt < 8; nt++)
#pragma unroll
                for (int e = 0; e < 4; e++) acc[mt][nt][e] = 0.f;

#pragma unroll 1
        for (int c = 0; c < 8; ++c) {
            const char* ab = smc + OFF_A + (c & 1) * 32768;
#pragma unroll
            for (int ks = 0; ks < 4; ks++) {
                uint32_t a[2][4];
#pragma unroll
                for (int mt = 0; mt < 2; mt++) {
                    const char* base = ab + (mrow + mt * 16 + g) * 128 + t4 * 4;
                    const int c0 = ((2 * ks) ^ g) * 16;
                    const int c1 = ((2 * ks + 1) ^ g) * 16;
                    a[mt][0] = rna_u(*(const float*)(base + c0));
                    a[mt][1] = rna_u(*(const float*)(base + 8 * 128 + c0));
                    a[mt][2] = rna_u(*(const float*)(base + c1));
                    a[mt][3] = rna_u(*(const float*)(base + 8 * 128 + c1));
                }
                const int kk = c * 4 + ks;
                uint4 bq[4];
#pragma unroll
                for (int i = 0; i < 4; i++)
                    bq[i] = *(const uint4*)(smc + OFF_W +
                             (((kk * 8) + qbase + i) * 32 + lane) * 16);
#pragma unroll
                for (int mt = 0; mt < 2; mt++) {
#pragma unroll
                    for (int nt = 0; nt < 8; nt++) {
                        uint32_t b0 = (nt & 1) ? bq[nt >> 1].z : bq[nt >> 1].x;
                        uint32_t b1 = (nt & 1) ? bq[nt >> 1].w : bq[nt >> 1].y;
                        MMA_TF32(acc[mt][nt], a[mt], b0, b1);
                    }
                }
            }
            __syncthreads();                       // all reads of buf (c&1) done
            if (c + 2 < 8) issue_stage<MODE>(smc, c & 1, c + 2, tid, A0, rbase);
            CP_COMMIT();
            CP_WAIT1();                            // stage c+1 landed (this thread)
            __syncthreads();                       // stage c+1 landed (all threads)
        }

        // epilogue: bias + LeakyReLU (+rna for MODE 0), direct STG
        const float* bs = (const float*)(smc + OFF_BIAS);
#pragma unroll
        for (int nt = 0; nt < 8; nt++) {
            const int col = ncol + nt * 8 + t4 * 2;
            const float b0 = bs[col], b1 = bs[col + 1];
#pragma unroll
            for (int mt = 0; mt < 2; mt++) {
                const int r0 = rbase + mrow + mt * 16 + g;
                float2 v0, v1;
                v0.x = lrelu(acc[mt][nt][0] + b0);
                v0.y = lrelu(acc[mt][nt][1] + b1);
                v1.x = lrelu(acc[mt][nt][2] + b0);
                v1.y = lrelu(acc[mt][nt][3] + b1);
                if (MODE == 0) {
                    v0.x = tf32_rna(v0.x); v0.y = tf32_rna(v0.y);
                    v1.x = tf32_rna(v1.x); v1.y = tf32_rna(v1.y);
                }
                *(float2*)(out + (size_t)r0 * 128 + col) = v0;
                *(float2*)(out + (size_t)(r0 + 8) * 128 + col) = v1;
            }
        }
    }
}

// ---------------- launch ----------------
extern "C" void kernel_launch(void* const* d_in, const int* in_sizes, int n_in,
                              void* d_out, int out_size) {
    const float* x_down = (const float*)d_in[0];
    const float* x_up   = (const float*)d_in[1];
    const void*  up_idx = d_in[2];
    const float* Wlin   = (const float*)d_in[3];
    const float* blin   = (const float*)d_in[4];
    const float* Wfus   = (const float*)d_in[5];
    const float* bfus   = (const float*)d_in[6];
    float* out = (float*)d_out;

    cudaFuncSetAttribute(gemm_tf32<0>, cudaFuncAttributeMaxDynamicSharedMemorySize, SMEM_BYTES);
    cudaFuncSetAttribute(gemm_tf32<1>, cudaFuncAttributeMaxDynamicSharedMemorySize, SMEM_BYTES);

    k_zero<<<1, 1>>>();
    k_detect<<<256, 256>>>((const unsigned*)up_idx, M2 / 2);
    k_convert<<<M2 / 256, 256>>>(up_idx, M2);
    k_prep_w<<<32768 / 256, 256>>>(Wlin, Wfus);

    gemm_tf32<0><<<GRID, THREADS, SMEM_BYTES>>>(x_down, blin, nullptr);
    gemm_tf32<1><<<GRID, THREADS, SMEM_BYTES>>>(x_up, bfus, out);
}